// round 1
// baseline (speedup 1.0000x reference)
#include <cuda_runtime.h>

// Problem constants
#define BSZ 8
#define CCH 128
#define NV  5
#define NH  224
#define NW  224
#define NK  2048
#define ND  64
#define HWSZ (NH*NW)          // 50176
#define VHW (NV*NH*NW)        // 250880

#define TILE 16               // points per block
#define THREADS 256

__global__ __launch_bounds__(THREADS, 2)
void peak_node_kernel(const float* __restrict__ fm,
                      const float* __restrict__ pos,
                      const float* __restrict__ W1,
                      const float* __restrict__ b1,
                      const float* __restrict__ W2,
                      const float* __restrict__ b2,
                      float* __restrict__ out)
{
    __shared__ float W1sh[CCH * ND];          // 32 KB, row-major [c][d]
    __shared__ float samp[TILE][CCH + 4];     // padded: avoid 2-way bank conflict on broadcast reads
    __shared__ float hsh[TILE][ND + 4];       // padded (stride 68 words: float4-aligned)
    __shared__ int   pbase[TILE];
    __shared__ int   pdx[TILE];
    __shared__ int   pdyw[TILE];
    __shared__ float pwx[TILE];
    __shared__ float pwy[TILE];

    const int t = threadIdx.x;

    // ---- stage W1 into shared (float4) ----
    {
        const float4* W1v = reinterpret_cast<const float4*>(W1);
        float4* W1sv = reinterpret_cast<float4*>(W1sh);
        #pragma unroll
        for (int i = t; i < (CCH * ND) / 4; i += THREADS)
            W1sv[i] = W1v[i];
    }

    // ---- per-point setup (first TILE threads) ----
    if (t < TILE) {
        int gp = blockIdx.x * TILE + t;
        float p0 = pos[gp * 3 + 0];
        float ry = pos[gp * 3 + 1];
        float cx = pos[gp * 3 + 2];
        int v = (int)p0;
        v = min(max(v, 0), NV - 1);
        float y0f = floorf(ry);
        float x0f = floorf(cx);
        float wy = ry - y0f;
        float wx = cx - x0f;
        int y0 = min(max((int)y0f, 0), NH - 1);
        int y1 = min(y0 + 1, NH - 1);
        int x0 = min(max((int)x0f, 0), NW - 1);
        int x1 = min(x0 + 1, NW - 1);
        int b = gp / NK;
        pbase[t] = b * (CCH * VHW) + v * HWSZ + y0 * NW + x0;
        pdx[t]   = x1 - x0;
        pdyw[t]  = (y1 - y0) * NW;
        pwx[t]   = wx;
        pwy[t]   = wy;
    }
    __syncthreads();

    // ---- phase 1: bilinear gather of TILE*CCH samples ----
    // item i: c = i & 127 (consecutive lanes -> consecutive c, conflict-free smem writes)
    #pragma unroll
    for (int it = 0; it < (TILE * CCH) / THREADS; ++it) {
        int i = it * THREADS + t;
        int c = i & (CCH - 1);
        int p = i >> 7;
        int base = pbase[p] + c * VHW;
        int dx = pdx[p];
        int dy = pdyw[p];
        float f00 = __ldg(fm + base);
        float f01 = __ldg(fm + base + dx);
        float f10 = __ldg(fm + base + dy);
        float f11 = __ldg(fm + base + dy + dx);
        float wx = pwx[p];
        float wy = pwy[p];
        float top = f00 + wx * (f01 - f00);
        float bot = f10 + wx * (f11 - f10);
        samp[p][c] = top + wy * (bot - top);
    }
    __syncthreads();

    // ---- phase 2: MLP. 16 threads per point, 4 dims each ----
    const int p  = t >> 4;            // 0..15
    const int db = (t & 15) * 4;      // 0,4,...,60

    // layer 1: h = relu(samp @ W1 + b1)
    float a0 = b1[db + 0];
    float a1 = b1[db + 1];
    float a2 = b1[db + 2];
    float a3 = b1[db + 3];
    #pragma unroll 8
    for (int c = 0; c < CCH; ++c) {
        float s = samp[p][c];
        float4 w = *reinterpret_cast<const float4*>(&W1sh[c * ND + db]);
        a0 = fmaf(s, w.x, a0);
        a1 = fmaf(s, w.y, a1);
        a2 = fmaf(s, w.z, a2);
        a3 = fmaf(s, w.w, a3);
    }
    float4 hv;
    hv.x = fmaxf(a0, 0.f);
    hv.y = fmaxf(a1, 0.f);
    hv.z = fmaxf(a2, 0.f);
    hv.w = fmaxf(a3, 0.f);
    *reinterpret_cast<float4*>(&hsh[p][db]) = hv;
    __syncthreads();

    // layer 2: out = h @ W2 + b2 (W2 via L1-resident __ldg)
    float o0 = __ldg(b2 + db + 0);
    float o1 = __ldg(b2 + db + 1);
    float o2 = __ldg(b2 + db + 2);
    float o3 = __ldg(b2 + db + 3);
    #pragma unroll 8
    for (int e = 0; e < ND; ++e) {
        float hval = hsh[p][e];
        float4 w = __ldg(reinterpret_cast<const float4*>(&W2[e * ND + db]));
        o0 = fmaf(hval, w.x, o0);
        o1 = fmaf(hval, w.y, o1);
        o2 = fmaf(hval, w.z, o2);
        o3 = fmaf(hval, w.w, o3);
    }

    // L2 norm across the point's 64 dims: partial sumsq, reduce over 16 lanes
    float ss = o0 * o0 + o1 * o1 + o2 * o2 + o3 * o3;
    #pragma unroll
    for (int m = 8; m >= 1; m >>= 1)
        ss += __shfl_xor_sync(0xffffffffu, ss, m);

    float nrm = sqrtf(ss);
    float inv = 1.0f / fmaxf(nrm, 1e-12f);

    int gp = blockIdx.x * TILE + p;
    float4 ov;
    ov.x = o0 * inv;
    ov.y = o1 * inv;
    ov.z = o2 * inv;
    ov.w = o3 * inv;
    *reinterpret_cast<float4*>(&out[gp * ND + db]) = ov;
}

extern "C" void kernel_launch(void* const* d_in, const int* in_sizes, int n_in,
                              void* d_out, int out_size)
{
    const float* fm  = (const float*)d_in[0];
    const float* pos = (const float*)d_in[1];
    const float* W1  = (const float*)d_in[2];
    const float* b1  = (const float*)d_in[3];
    const float* W2  = (const float*)d_in[4];
    const float* b2  = (const float*)d_in[5];
    float* out = (float*)d_out;

    dim3 grid((BSZ * NK) / TILE);   // 1024 blocks
    dim3 block(THREADS);
    peak_node_kernel<<<grid, block>>>(fm, pos, W1, b1, W2, b2, out);
}